// round 1
// baseline (speedup 1.0000x reference)
#include <cuda_runtime.h>
#include <cstdint>
#include <cstddef>

#define N_NODES 1024
#define F_IN    32
#define HID     64
#define OUT     32

// Scratch for the precomputed half-GEMMs (device globals: no allocation).
__device__ float g_A[N_NODES * HID];   // A[i,h] = Emb[i,:] . W1[h, :F]
__device__ float g_B[N_NODES * HID];   // B[j,h] = Emb[j,:] . W1[h, F:]

// ---------------------------------------------------------------------------
// Kernel 1: A/B precompute (tiny: 1024x64x32 x2 = ~8 MFLOP)
// ---------------------------------------------------------------------------
__global__ void precompute_AB(const float* __restrict__ Emb,
                              const float* __restrict__ W1) {
    int idx = blockIdx.x * blockDim.x + threadIdx.x;   // 0 .. N*HID-1
    int i = idx >> 6;       // node
    int h = idx & 63;       // hidden unit
    const float* er = Emb + i * F_IN;
    const float* wr = W1 + h * (2 * F_IN);
    float sa = 0.f, sb = 0.f;
#pragma unroll
    for (int f = 0; f < F_IN; ++f) {
        float e = er[f];
        sa = fmaf(e, wr[f], sa);
        sb = fmaf(e, wr[F_IN + f], sb);
    }
    g_A[idx] = sa;
    g_B[idx] = sb;
}

// ---------------------------------------------------------------------------
// f32x2 packed-math helpers (Blackwell; ptxas won't emit FFMA2 from C++)
// ---------------------------------------------------------------------------
__device__ __forceinline__ unsigned long long pack2(float lo, float hi) {
    unsigned long long r;
    asm("mov.b64 %0, {%1, %2};"
        : "=l"(r) : "r"(__float_as_uint(lo)), "r"(__float_as_uint(hi)));
    return r;
}

__device__ __forceinline__ void unpack2(unsigned long long v, float& lo, float& hi) {
    unsigned a, b;
    asm("mov.b64 {%0, %1}, %2;" : "=r"(a), "=r"(b) : "l"(v));
    lo = __uint_as_float(a);
    hi = __uint_as_float(b);
}

__device__ __forceinline__ unsigned long long lds_u64(unsigned addr) {
    unsigned long long r;
    asm volatile("ld.shared.b64 %0, [%1];" : "=l"(r) : "r"(addr));
    return r;
}

#define FFMA2(acc, a, b) \
    asm("fma.rn.f32x2 %0, %1, %2, %0;" : "+l"(acc) : "l"(a), "l"(b))

// swish(x) = x * sigmoid(x) via EX2 + RCP (rel err ~1e-6, well under 1e-3)
__device__ __forceinline__ float swish_fast(float x) {
    float e;
    asm("ex2.approx.f32 %0, %1;" : "=f"(e) : "f"(x * (-1.442695040888963f)));
    float r;
    asm("rcp.approx.f32 %0, %1;" : "=f"(r) : "f"(1.0f + e));
    return x * r;
}

// ---------------------------------------------------------------------------
// Kernel 2: fused per-edge MLP.
// Block: 256 threads = 8 warps. Warp w owns i = ibase + w; lane owns j and
// j+32 (2 edges/thread, sharing the per-h W2 LDS.64 broadcast loads).
// Tile: 8 i x 64 j per block -> grid (16, 128).
// ---------------------------------------------------------------------------
__global__ __launch_bounds__(256)
void edge_mlp_kernel(const float* __restrict__ Edges,
                     const float* __restrict__ Coords,
                     const float* __restrict__ b1,
                     const float* __restrict__ W2,
                     const float* __restrict__ b2,
                     float* __restrict__ out) {
    __shared__ __align__(16) float  Bs[64][68];   // stride 68: conflict-free .128
    __shared__ __align__(16) float  As[8][64];
    __shared__ __align__(16) float2 W2p[HID][16]; // W2p[h][o2] = (W2[2o2,h], W2[2o2+1,h])
    __shared__ __align__(16) float  b1s[HID];
    __shared__ float b2s[OUT];
    __shared__ float Cj[3][64];

    const int tid  = threadIdx.x;
    const int lane = tid & 31;
    const int warp = tid >> 5;
    const int jbase = blockIdx.x * 64;
    const int ibase = blockIdx.y * 8;

    // ---- prologue: stage tiles ----
    for (int idx = tid; idx < 64 * HID; idx += 256) {
        int jj = idx >> 6, h = idx & 63;
        Bs[jj][h] = g_B[(jbase + jj) * HID + h];
    }
    for (int idx = tid; idx < 8 * HID; idx += 256) {
        int ii = idx >> 6, h = idx & 63;
        As[ii][h] = g_A[(ibase + ii) * HID + h];
    }
    for (int idx = tid; idx < HID * 16; idx += 256) {
        int h = idx >> 4, o2 = idx & 15;
        W2p[h][o2] = make_float2(W2[(2 * o2) * HID + h],
                                 W2[(2 * o2 + 1) * HID + h]);
    }
    if (tid < HID) b1s[tid] = b1[tid];
    if (tid < OUT) b2s[tid] = b2[tid];
    if (tid < 64) {
        Cj[0][tid] = Coords[(jbase + tid) * 3 + 0];
        Cj[1][tid] = Coords[(jbase + tid) * 3 + 1];
        Cj[2][tid] = Coords[(jbase + tid) * 3 + 2];
    }
    __syncthreads();

    const int i  = ibase + warp;
    const int j0 = jbase + lane;
    const int j1 = j0 + 32;

    const float cx = Coords[i * 3 + 0];
    const float cy = Coords[i * 3 + 1];
    const float cz = Coords[i * 3 + 2];

    float dx = cx - Cj[0][lane], dy = cy - Cj[1][lane], dz = cz - Cj[2][lane];
    float d2 = dx * dx + dy * dy + dz * dz;
    float dist0 = (d2 > 0.f) ? d2 * rsqrtf(d2) : 0.f;
    dx = cx - Cj[0][lane + 32]; dy = cy - Cj[1][lane + 32]; dz = cz - Cj[2][lane + 32];
    d2 = dx * dx + dy * dy + dz * dz;
    float dist1 = (d2 > 0.f) ? d2 * rsqrtf(d2) : 0.f;

    const float w0 = Edges[(size_t)i * N_NODES + j0] * dist0;
    const float w1 = Edges[(size_t)i * N_NODES + j1] * dist1;

    // ---- main loop: h1 = swish(...), acc += h1 (outer-prod with W2 rows) ----
    unsigned long long acc0[16], acc1[16];
#pragma unroll
    for (int o2 = 0; o2 < 16; ++o2) { acc0[o2] = 0ull; acc1[o2] = 0ull; }

    const unsigned w2sm = (unsigned)__cvta_generic_to_shared(&W2p[0][0]);
    const float* Arow  = &As[warp][0];
    const float* Brow0 = &Bs[lane][0];
    const float* Brow1 = &Bs[lane + 32][0];

#pragma unroll 2
    for (int h4 = 0; h4 < HID; h4 += 4) {
        float4 a4  = *(const float4*)(Arow + h4);
        float4 p4  = *(const float4*)(Brow0 + h4);
        float4 q4  = *(const float4*)(Brow1 + h4);
        float4 bb4 = *(const float4*)(b1s + h4);
        float av[4] = {a4.x, a4.y, a4.z, a4.w};
        float pv[4] = {p4.x, p4.y, p4.z, p4.w};
        float qv[4] = {q4.x, q4.y, q4.z, q4.w};
        float bv[4] = {bb4.x, bb4.y, bb4.z, bb4.w};
#pragma unroll
        for (int k = 0; k < 4; ++k) {
            float x0 = fmaf(w0, av[k] + pv[k], bv[k]);
            float x1 = fmaf(w1, av[k] + qv[k], bv[k]);
            float g0 = swish_fast(x0);
            float g1 = swish_fast(x1);
            unsigned long long g20 = pack2(g0, g0);
            unsigned long long g21 = pack2(g1, g1);
            unsigned base = w2sm + (unsigned)(h4 + k) * (16 * 8);
#pragma unroll
            for (int o2 = 0; o2 < 16; ++o2) {
                unsigned long long wv = lds_u64(base + o2 * 8);
                FFMA2(acc0[o2], g20, wv);
                FFMA2(acc1[o2], g21, wv);
            }
        }
    }

    // ---- epilogue: + b2, swish, store (8x float4 per edge) ----
    const size_t base0 = ((size_t)i * N_NODES + j0) * OUT;
    const size_t base1 = ((size_t)i * N_NODES + j1) * OUT;
#pragma unroll
    for (int o4 = 0; o4 < 8; ++o4) {
        float a, b, c, d;
        unpack2(acc0[2 * o4 + 0], a, b);
        unpack2(acc0[2 * o4 + 1], c, d);
        float4 v;
        v.x = swish_fast(a + b2s[4 * o4 + 0]);
        v.y = swish_fast(b + b2s[4 * o4 + 1]);
        v.z = swish_fast(c + b2s[4 * o4 + 2]);
        v.w = swish_fast(d + b2s[4 * o4 + 3]);
        *(float4*)(out + base0 + 4 * o4) = v;

        unpack2(acc1[2 * o4 + 0], a, b);
        unpack2(acc1[2 * o4 + 1], c, d);
        v.x = swish_fast(a + b2s[4 * o4 + 0]);
        v.y = swish_fast(b + b2s[4 * o4 + 1]);
        v.z = swish_fast(c + b2s[4 * o4 + 2]);
        v.w = swish_fast(d + b2s[4 * o4 + 3]);
        *(float4*)(out + base1 + 4 * o4) = v;
    }
}

// ---------------------------------------------------------------------------
// Harness entry. Inputs (metadata order): Edges, Coordinates, Embeddings,
// W1, b1, W2, b2. Output: float32 (N, N, OUT).
// ---------------------------------------------------------------------------
extern "C" void kernel_launch(void* const* d_in, const int* in_sizes, int n_in,
                              void* d_out, int out_size) {
    const float* Edges  = (const float*)d_in[0];
    const float* Coords = (const float*)d_in[1];
    const float* Emb    = (const float*)d_in[2];
    const float* W1     = (const float*)d_in[3];
    const float* b1     = (const float*)d_in[4];
    const float* W2     = (const float*)d_in[5];
    const float* b2     = (const float*)d_in[6];
    float* out = (float*)d_out;

    precompute_AB<<<(N_NODES * HID) / 256, 256>>>(Emb, W1);

    dim3 grid(N_NODES / 64, N_NODES / 8);
    edge_mlp_kernel<<<grid, 256>>>(Edges, Coords, b1, W2, b2, out);
}

// round 3
// speedup vs baseline: 1.3424x; 1.3424x over previous
#include <cuda_runtime.h>
#include <cuda_bf16.h>
#include <cstdint>
#include <cstddef>

#define N_NODES 1024
#define F_IN    32
#define HID     64
#define OUT     32
#define I_TILE  8
#define J_TILE  16

// Feature gate: tcgen05 only exists in arch-specific ('a') or family ('f')
// compilation passes. The bench's device pass is plain compute_103, where
// these macros are undefined -> scalar fallback is compiled instead.
#if defined(__CUDA_ARCH__) && (defined(__CUDA_ARCH_FEAT_SM103_ALL) || \
                               defined(__CUDA_ARCH_FEAT_SM100_ALL) || \
                               defined(__CUDA_ARCH_FAMILY_SPECIFIC__))
#define USE_TC 1
#else
#define USE_TC 0
#endif

// Scratch for the precomputed half-GEMMs (device globals: no allocation).
__device__ float g_A[N_NODES * HID];   // A[i,h] = Emb[i,:] . W1[h, :F]
__device__ float g_B[N_NODES * HID];   // B[j,h] = Emb[j,:] . W1[h, F:]

// ---------------------------------------------------------------------------
// Kernel 1: A/B precompute (tiny: ~8 MFLOP)
// ---------------------------------------------------------------------------
__global__ void precompute_AB(const float* __restrict__ Emb,
                              const float* __restrict__ W1) {
    int idx = blockIdx.x * blockDim.x + threadIdx.x;
    int i = idx >> 6;
    int h = idx & 63;
    const float* er = Emb + i * F_IN;
    const float* wr = W1 + h * (2 * F_IN);
    float sa = 0.f, sb = 0.f;
#pragma unroll
    for (int f = 0; f < F_IN; ++f) {
        float e = er[f];
        sa = fmaf(e, wr[f], sa);
        sb = fmaf(e, wr[F_IN + f], sb);
    }
    g_A[idx] = sa;
    g_B[idx] = sb;
}

// ---------------------------------------------------------------------------
// Helpers
// ---------------------------------------------------------------------------
__device__ __forceinline__ unsigned smem_u32(const void* p) {
    unsigned a;
    asm("{ .reg .u64 t; cvta.to.shared.u64 t, %1; cvt.u32.u64 %0, t; }"
        : "=r"(a) : "l"(p));
    return a;
}

__device__ __forceinline__ unsigned long long pack2(float lo, float hi) {
    unsigned long long r;
    asm("mov.b64 %0, {%1, %2};"
        : "=l"(r) : "r"(__float_as_uint(lo)), "r"(__float_as_uint(hi)));
    return r;
}

__device__ __forceinline__ void unpack2(unsigned long long v, float& lo, float& hi) {
    unsigned a, b;
    asm("mov.b64 {%0, %1}, %2;" : "=r"(a), "=r"(b) : "l"(v));
    lo = __uint_as_float(a);
    hi = __uint_as_float(b);
}

__device__ __forceinline__ unsigned long long lds_u64(unsigned addr) {
    unsigned long long r;
    asm volatile("ld.shared.b64 %0, [%1];" : "=l"(r) : "r"(addr));
    return r;
}

#define FFMA2(acc, a, b) \
    asm("fma.rn.f32x2 %0, %1, %2, %0;" : "+l"(acc) : "l"(a), "l"(b))

// swish(x) = x * sigmoid(x) via EX2 + RCP (rel err ~1e-6)
__device__ __forceinline__ float swish_fast(float x) {
    float e;
    asm("ex2.approx.f32 %0, %1;" : "=f"(e) : "f"(x * (-1.442695040888963f)));
    float r;
    asm("rcp.approx.f32 %0, %1;" : "=f"(r) : "f"(1.0f + e));
    return x * r;
}

#if USE_TC
__device__ __forceinline__ bool elect_one() {
    unsigned pred;
    asm volatile("{\n\t.reg .pred p;\n\telect.sync _|p, 0xFFFFFFFF;\n\t"
                 "selp.b32 %0, 1, 0, p;\n\t}" : "=r"(pred));
    return pred != 0;
}

__device__ __forceinline__ void mbar_init(unsigned addr, unsigned cnt) {
    asm volatile("mbarrier.init.shared.b64 [%0], %1;" :: "r"(addr), "r"(cnt) : "memory");
}

__device__ __forceinline__ void mbar_inval(unsigned addr) {
    asm volatile("mbarrier.inval.shared.b64 [%0];" :: "r"(addr) : "memory");
}

__device__ __forceinline__ void mbar_wait(unsigned addr, unsigned parity) {
    asm volatile(
        "{\n\t.reg .pred P;\n\t"
        "WL_%=:\n\t"
        "mbarrier.try_wait.parity.acquire.cta.shared::cta.b64 P, [%0], %1, 0x989680;\n\t"
        "@P bra.uni WD_%=;\n\t"
        "bra.uni WL_%=;\n\t"
        "WD_%=:\n\t}"
        :: "r"(addr), "r"(parity) : "memory");
}

__device__ __forceinline__ unsigned long long sdesc(unsigned addr) {
    const unsigned long long base =
        (2ull << 61) | (1ull << 46) | (64ull << 32) | (1ull << 16);
    return base | ((unsigned long long)(addr >> 4) & 0x3FFF);
}

#define MMA_IDESC ((1u << 4) | (1u << 7) | (1u << 10) | ((OUT / 8) << 17) | (8u << 24))

__device__ __forceinline__ void mma_f16_ss(unsigned d_tmem,
                                           unsigned long long a_desc,
                                           unsigned long long b_desc,
                                           unsigned en) {
    asm volatile(
        "{\n\t.reg .pred p;\n\t"
        "setp.ne.u32 p, %5, 0;\n\t"
        "tcgen05.mma.cta_group::1.kind::f16 [%0], %1, %2, %3, {%4, %4, %4, %4}, p;\n\t"
        "}"
        :: "r"(d_tmem), "l"(a_desc), "l"(b_desc), "r"(MMA_IDESC), "r"(0u), "r"(en)
        : "memory");
}
#endif  // USE_TC

__device__ __forceinline__ unsigned cvt2bf16(float hi, float lo) {
    unsigned r;
    asm("cvt.rn.bf16x2.f32 %0, %1, %2;" : "=r"(r) : "f"(hi), "f"(lo));
    return r;
}

// ---------------------------------------------------------------------------
// Dynamic SMEM layout. Tensor path uses all of it; fallback uses the front.
// ---------------------------------------------------------------------------
#define SM_TMEM 0
#define SM_MBAR 8
#define SM_AHI  1024
#define SM_ALO  (SM_AHI + 128 * 128)
#define SM_WHI  (SM_ALO + 128 * 128)
#define SM_WLO  (SM_WHI + 32 * 128)
#define SM_TOTAL (SM_WLO + 32 * 128)     // 41984 bytes (< 48K, no opt-in)

// Fallback layout (within the same dynamic buffer)
#define FB_W2P  0                         // float2 W2p[HID][16]  = 8192 B
#define FB_B1   (FB_W2P + HID * 16 * 8)   // float  b1s[HID]      = 256 B
#define FB_B2   (FB_B1 + HID * 4)         // float  b2s[OUT]      = 128 B

#define SWZ(off) ((off) ^ (((off) >> 3) & 0x70))

// ---------------------------------------------------------------------------
// Kernel 2: fused edge MLP. Block = 128 threads, tile = 8 i x 16 j.
// ---------------------------------------------------------------------------
__global__ __launch_bounds__(128)
void edge_mlp_tc(const float* __restrict__ Edges,
                 const float* __restrict__ Coords,
                 const float* __restrict__ b1,
                 const float* __restrict__ W2,
                 const float* __restrict__ b2,
                 float* __restrict__ out) {
    extern __shared__ char smem[];
    const int tid  = threadIdx.x;
    const int lane = tid & 31;
    const int warp = tid >> 5;
    const int jbase = blockIdx.x * J_TILE;
    const int ibase = blockIdx.y * I_TILE;

    // per-edge weight (common to both paths)
    const int m = tid;
    const int i = ibase + (m >> 4);
    const int j = jbase + (m & 15);

    float dx = Coords[i * 3 + 0] - Coords[j * 3 + 0];
    float dy = Coords[i * 3 + 1] - Coords[j * 3 + 1];
    float dz = Coords[i * 3 + 2] - Coords[j * 3 + 2];
    float d2 = dx * dx + dy * dy + dz * dz;
    float dist = (d2 > 0.f) ? d2 * rsqrtf(d2) : 0.f;
    const float w = Edges[(size_t)i * N_NODES + j] * dist;

    const float4* Ar  = (const float4*)(g_A + i * HID);
    const float4* Br  = (const float4*)(g_B + j * HID);
    const float4* b1v = (const float4*)b1;

#if USE_TC
    // ===================== tcgen05 path =====================
    const unsigned sb = smem_u32(smem);
    if (warp == 0) {
        asm volatile("tcgen05.alloc.cta_group::1.sync.aligned.shared::cta.b32 [%0], %1;"
                     :: "r"(sb + SM_TMEM), "r"(32u) : "memory");
        asm volatile("tcgen05.relinquish_alloc_permit.cta_group::1.sync.aligned;");
    }
    if (tid == 0) mbar_init(sb + SM_MBAR, 1);

    // W2 -> bf16 hi/lo tiles (SW128 K-major, 128B rows)
    for (int p = tid; p < OUT * 32; p += 128) {
        int o = p >> 5, h2 = p & 31;
        float w0 = W2[o * HID + 2 * h2];
        float w1 = W2[o * HID + 2 * h2 + 1];
        unsigned hi = cvt2bf16(w1, w0);
        float r0 = w0 - __uint_as_float(hi << 16);
        float r1 = w1 - __uint_as_float(hi & 0xFFFF0000u);
        unsigned lo = cvt2bf16(r1, r0);
        unsigned off = (unsigned)(o * 128 + h2 * 4);
        unsigned sw = SWZ(off);
        *(unsigned*)(smem + SM_WHI + sw) = hi;
        *(unsigned*)(smem + SM_WLO + sw) = lo;
    }

    // h1 = swish(w*(A+B)+b1), split hi/lo into smem (row m, SW128)
#pragma unroll
    for (int c = 0; c < 16; ++c) {
        float4 a  = __ldg(Ar + c);
        float4 bb = __ldg(Br + c);
        float4 bv = __ldg(b1v + c);
        float g0 = swish_fast(fmaf(w, a.x + bb.x, bv.x));
        float g1 = swish_fast(fmaf(w, a.y + bb.y, bv.y));
        float g2 = swish_fast(fmaf(w, a.z + bb.z, bv.z));
        float g3 = swish_fast(fmaf(w, a.w + bb.w, bv.w));
        unsigned hi01 = cvt2bf16(g1, g0);
        unsigned hi23 = cvt2bf16(g3, g2);
        float r0 = g0 - __uint_as_float(hi01 << 16);
        float r1 = g1 - __uint_as_float(hi01 & 0xFFFF0000u);
        float r2 = g2 - __uint_as_float(hi23 << 16);
        float r3 = g3 - __uint_as_float(hi23 & 0xFFFF0000u);
        unsigned lo01 = cvt2bf16(r1, r0);
        unsigned lo23 = cvt2bf16(r3, r2);
        unsigned off = (unsigned)(m * 128 + c * 8);
        unsigned sw = SWZ(off);
        *(uint2*)(smem + SM_AHI + sw) = make_uint2(hi01, hi23);
        *(uint2*)(smem + SM_ALO + sw) = make_uint2(lo01, lo23);
    }

    asm volatile("fence.proxy.async.shared::cta;" ::: "memory");
    __syncthreads();

    unsigned tmem;
    asm("ld.shared.b32 %0, [%1];" : "=r"(tmem) : "r"(sb + SM_TMEM));

    if (warp == 0 && elect_one()) {
        unsigned long long ahi = sdesc(sb + SM_AHI);
        unsigned long long alo = sdesc(sb + SM_ALO);
        unsigned long long whi = sdesc(sb + SM_WHI);
        unsigned long long wlo = sdesc(sb + SM_WLO);
        unsigned en = 0;
#pragma unroll
        for (int k = 0; k < 4; ++k) { mma_f16_ss(tmem, ahi + 2 * k, whi + 2 * k, en); en = 1; }
#pragma unroll
        for (int k = 0; k < 4; ++k) { mma_f16_ss(tmem, alo + 2 * k, whi + 2 * k, 1); }
#pragma unroll
        for (int k = 0; k < 4; ++k) { mma_f16_ss(tmem, ahi + 2 * k, wlo + 2 * k, 1); }
        asm volatile(
            "tcgen05.commit.cta_group::1.mbarrier::arrive::one.shared::cluster.b64 [%0];"
            :: "r"(sb + SM_MBAR) : "memory");
    }

    mbar_wait(sb + SM_MBAR, 0);
    asm volatile("tcgen05.fence::after_thread_sync;" ::: "memory");

    unsigned d[32];
    asm volatile(
        "tcgen05.ld.sync.aligned.32x32b.x32.b32 "
        "{%0, %1, %2, %3, %4, %5, %6, %7, "
        " %8, %9, %10, %11, %12, %13, %14, %15, "
        " %16, %17, %18, %19, %20, %21, %22, %23, "
        " %24, %25, %26, %27, %28, %29, %30, %31}, [%32];"
        : "=r"(d[0]),  "=r"(d[1]),  "=r"(d[2]),  "=r"(d[3]),
          "=r"(d[4]),  "=r"(d[5]),  "=r"(d[6]),  "=r"(d[7]),
          "=r"(d[8]),  "=r"(d[9]),  "=r"(d[10]), "=r"(d[11]),
          "=r"(d[12]), "=r"(d[13]), "=r"(d[14]), "=r"(d[15]),
          "=r"(d[16]), "=r"(d[17]), "=r"(d[18]), "=r"(d[19]),
          "=r"(d[20]), "=r"(d[21]), "=r"(d[22]), "=r"(d[23]),
          "=r"(d[24]), "=r"(d[25]), "=r"(d[26]), "=r"(d[27]),
          "=r"(d[28]), "=r"(d[29]), "=r"(d[30]), "=r"(d[31])
        : "r"(tmem));
    asm volatile("tcgen05.wait::ld.sync.aligned;" ::: "memory");
    asm volatile("tcgen05.fence::before_thread_sync;" ::: "memory");

    const size_t orow = ((size_t)i * N_NODES + j) * OUT;
    const float4* b2v = (const float4*)b2;
#pragma unroll
    for (int q = 0; q < 8; ++q) {
        float4 bq = __ldg(b2v + q);
        float4 v;
        v.x = swish_fast(__uint_as_float(d[4 * q + 0]) + bq.x);
        v.y = swish_fast(__uint_as_float(d[4 * q + 1]) + bq.y);
        v.z = swish_fast(__uint_as_float(d[4 * q + 2]) + bq.z);
        v.w = swish_fast(__uint_as_float(d[4 * q + 3]) + bq.w);
        *(float4*)(out + orow + 4 * q) = v;
    }

    __syncthreads();
    if (tid == 0) mbar_inval(sb + SM_MBAR);
    __syncthreads();
    if (warp == 0) {
        asm volatile("tcgen05.dealloc.cta_group::1.sync.aligned.b32 %0, %1;"
                     :: "r"(tmem), "r"(32u));
    }
#else
    // ===================== scalar FFMA2 fallback =====================
    // Stage W2 as (h, o-pair) float2 for broadcast LDS.64 loads.
    float2* W2p = (float2*)(smem + FB_W2P);
    float*  b1s = (float*)(smem + FB_B1);
    float*  b2s = (float*)(smem + FB_B2);
    for (int p = tid; p < HID * 16; p += 128) {
        int h = p >> 4, o2 = p & 15;
        W2p[h * 16 + o2] = make_float2(W2[(2 * o2) * HID + h],
                                       W2[(2 * o2 + 1) * HID + h]);
    }
    if (tid < HID) b1s[tid] = b1[tid];
    if (tid < OUT) b2s[tid] = b2[tid];
    __syncthreads();

    unsigned long long acc[16];
#pragma unroll
    for (int o2 = 0; o2 < 16; ++o2) acc[o2] = 0ull;

    const unsigned w2sm = smem_u32(W2p);

#pragma unroll 4
    for (int c = 0; c < 16; ++c) {
        float4 a  = __ldg(Ar + c);
        float4 bb = __ldg(Br + c);
        float4 bv = __ldg(b1v + c);
        float av[4] = {a.x, a.y, a.z, a.w};
        float pv[4] = {bb.x, bb.y, bb.z, bb.w};
        float cv[4] = {bv.x, bv.y, bv.z, bv.w};
#pragma unroll
        for (int k = 0; k < 4; ++k) {
            float g = swish_fast(fmaf(w, av[k] + pv[k], cv[k]));
            unsigned long long g2 = pack2(g, g);
            unsigned base = w2sm + (unsigned)(4 * c + k) * (16 * 8);
#pragma unroll
            for (int o2 = 0; o2 < 16; ++o2) {
                unsigned long long wv = lds_u64(base + o2 * 8);
                FFMA2(acc[o2], g2, wv);
            }
        }
    }

    const size_t orow = ((size_t)i * N_NODES + j) * OUT;
#pragma unroll
    for (int o4 = 0; o4 < 8; ++o4) {
        float a, b, c, d;
        unpack2(acc[2 * o4 + 0], a, b);
        unpack2(acc[2 * o4 + 1], c, d);
        float4 v;
        v.x = swish_fast(a + b2s[4 * o4 + 0]);
        v.y = swish_fast(b + b2s[4 * o4 + 1]);
        v.z = swish_fast(c + b2s[4 * o4 + 2]);
        v.w = swish_fast(d + b2s[4 * o4 + 3]);
        *(float4*)(out + orow + 4 * o4) = v;
    }
#endif
}

// ---------------------------------------------------------------------------
// Harness entry. Inputs: Edges, Coordinates, Embeddings, W1, b1, W2, b2.
// Output: float32 (N, N, OUT).
// ---------------------------------------------------------------------------
extern "C" void kernel_launch(void* const* d_in, const int* in_sizes, int n_in,
                              void* d_out, int out_size) {
    const float* Edges  = (const float*)d_in[0];
    const float* Coords = (const float*)d_in[1];
    const float* Emb    = (const float*)d_in[2];
    const float* W1     = (const float*)d_in[3];
    const float* b1     = (const float*)d_in[4];
    const float* W2     = (const float*)d_in[5];
    const float* b2     = (const float*)d_in[6];
    float* out = (float*)d_out;

    precompute_AB<<<(N_NODES * HID) / 256, 256>>>(Emb, W1);

    dim3 grid(N_NODES / J_TILE, N_NODES / I_TILE);   // (64, 128)
    edge_mlp_tc<<<grid, 128, SM_TOTAL>>>(Edges, Coords, b1, W2, b2, out);
}

// round 4
// speedup vs baseline: 1.8227x; 1.3578x over previous
#include <cuda_runtime.h>
#include <cuda_bf16.h>
#include <cstdint>
#include <cstddef>

#define N_NODES 1024
#define F_IN    32
#define HID     64
#define OUT     32
#define I_TILE  8
#define J_TILE  16
#define JITERS  8     // j-tiles per block

#if defined(__CUDA_ARCH__) && (defined(__CUDA_ARCH_FEAT_SM103_ALL) || \
                               defined(__CUDA_ARCH_FEAT_SM100_ALL) || \
                               defined(__CUDA_ARCH_FAMILY_SPECIFIC__))
#define USE_TC 1
#else
#define USE_TC 0
#endif

__device__ float g_A[N_NODES * HID];   // A[i,h] = Emb[i,:] . W1[h, :F]
__device__ float g_B[N_NODES * HID];   // B[j,h] = Emb[j,:] . W1[h, F:]

// ---------------------------------------------------------------------------
// Kernel 1: A/B precompute (tiny)
// ---------------------------------------------------------------------------
__global__ void precompute_AB(const float* __restrict__ Emb,
                              const float* __restrict__ W1) {
    int idx = blockIdx.x * blockDim.x + threadIdx.x;
    int i = idx >> 6;
    int h = idx & 63;
    const float* er = Emb + i * F_IN;
    const float* wr = W1 + h * (2 * F_IN);
    float sa = 0.f, sb = 0.f;
#pragma unroll
    for (int f = 0; f < F_IN; ++f) {
        float e = er[f];
        sa = fmaf(e, wr[f], sa);
        sb = fmaf(e, wr[F_IN + f], sb);
    }
    g_A[idx] = sa;
    g_B[idx] = sb;
}

// ---------------------------------------------------------------------------
// Helpers
// ---------------------------------------------------------------------------
__device__ __forceinline__ unsigned smem_u32(const void* p) {
    unsigned a;
    asm("{ .reg .u64 t; cvta.to.shared.u64 t, %1; cvt.u32.u64 %0, t; }"
        : "=r"(a) : "l"(p));
    return a;
}

__device__ __forceinline__ unsigned long long pack2(float lo, float hi) {
    unsigned long long r;
    asm("mov.b64 %0, {%1, %2};"
        : "=l"(r) : "r"(__float_as_uint(lo)), "r"(__float_as_uint(hi)));
    return r;
}

__device__ __forceinline__ void unpack2(unsigned long long v, float& lo, float& hi) {
    unsigned a, b;
    asm("mov.b64 {%0, %1}, %2;" : "=r"(a), "=r"(b) : "l"(v));
    lo = __uint_as_float(a);
    hi = __uint_as_float(b);
}

__device__ __forceinline__ unsigned long long lds_u64(unsigned addr) {
    unsigned long long r;
    asm volatile("ld.shared.b64 %0, [%1];" : "=l"(r) : "r"(addr));
    return r;
}

#define FFMA2(acc, a, b) \
    asm("fma.rn.f32x2 %0, %1, %2, %0;" : "+l"(acc) : "l"(a), "l"(b))

__device__ __forceinline__ float swish_fast(float x) {
    float e;
    asm("ex2.approx.f32 %0, %1;" : "=f"(e) : "f"(x * (-1.442695040888963f)));
    float r;
    asm("rcp.approx.f32 %0, %1;" : "=f"(r) : "f"(1.0f + e));
    return x * r;
}

__device__ __forceinline__ unsigned cvt2bf16(float hi, float lo) {
    unsigned r;
    asm("cvt.rn.bf16x2.f32 %0, %1, %2;" : "=r"(r) : "f"(hi), "f"(lo));
    return r;
}

#if USE_TC
__device__ __forceinline__ bool elect_one() {
    unsigned pred;
    asm volatile("{\n\t.reg .pred p;\n\telect.sync _|p, 0xFFFFFFFF;\n\t"
                 "selp.b32 %0, 1, 0, p;\n\t}" : "=r"(pred));
    return pred != 0;
}

__device__ __forceinline__ void mbar_init(unsigned addr, unsigned cnt) {
    asm volatile("mbarrier.init.shared.b64 [%0], %1;" :: "r"(addr), "r"(cnt) : "memory");
}

__device__ __forceinline__ void mbar_inval(unsigned addr) {
    asm volatile("mbarrier.inval.shared.b64 [%0];" :: "r"(addr) : "memory");
}

__device__ __forceinline__ void mbar_wait(unsigned addr, unsigned parity) {
    asm volatile(
        "{\n\t.reg .pred P;\n\t"
        "WL_%=:\n\t"
        "mbarrier.try_wait.parity.acquire.cta.shared::cta.b64 P, [%0], %1, 0x989680;\n\t"
        "@P bra.uni WD_%=;\n\t"
        "bra.uni WL_%=;\n\t"
        "WD_%=:\n\t}"
        :: "r"(addr), "r"(parity) : "memory");
}

// SW128 K-major smem descriptor: layout=2, version=1, SBO=64, LBO=1
__device__ __forceinline__ unsigned long long sdesc(unsigned addr) {
    const unsigned long long base =
        (2ull << 61) | (1ull << 46) | (64ull << 32) | (1ull << 16);
    return base | ((unsigned long long)(addr >> 4) & 0x3FFF);
}

// idesc kind::f16: dtype=F32, atype=btype=BF16, N=32, M=128 -> 0x8080490
#define MMA_IDESC ((1u << 4) | (1u << 7) | (1u << 10) | ((OUT / 8) << 17) | (8u << 24))

__device__ __forceinline__ void mma_f16_ss(unsigned d_tmem,
                                           unsigned long long a_desc,
                                           unsigned long long b_desc,
                                           unsigned en) {
    asm volatile(
        "{\n\t.reg .pred p;\n\t"
        "setp.ne.u32 p, %5, 0;\n\t"
        "tcgen05.mma.cta_group::1.kind::f16 [%0], %1, %2, %3, {%4, %4, %4, %4}, p;\n\t"
        "}"
        :: "r"(d_tmem), "l"(a_desc), "l"(b_desc), "r"(MMA_IDESC), "r"(0u), "r"(en)
        : "memory");
}
#endif  // USE_TC

// ---------------------------------------------------------------------------
// Dynamic SMEM layout
// ---------------------------------------------------------------------------
#define SM_TMEM 0
#define SM_MBAR 8
#define SM_AHI  1024
#define SM_ALO  (SM_AHI + 128 * 128)       // 17408
#define SM_WHI  (SM_ALO + 128 * 128)       // 33792
#define SM_WLO  (SM_WHI + 32 * 128)        // 37888
#define SM_BS   (SM_WLO + 32 * 128)        // 41984 ; 16 rows x 68 floats
#define SM_TOTAL (SM_BS + 16 * 68 * 4)     // 46336 bytes

// Fallback layout (front of same buffer)
#define FB_W2P  0
#define FB_B1   (FB_W2P + HID * 16 * 8)
#define FB_B2   (FB_B1 + HID * 4)

#define SWZ(off) ((off) ^ (((off) >> 3) & 0x70))

// ---------------------------------------------------------------------------
// Kernel 2: fused edge MLP, persistent over 8 j-tiles per block.
// Block = 128 thr; per iter: tile 8 i x 16 j (M=128), N=32, K=64.
// ---------------------------------------------------------------------------
__global__ __launch_bounds__(128)
void edge_mlp_tc(const float* __restrict__ Edges,
                 const float* __restrict__ Coords,
                 const float* __restrict__ b1,
                 const float* __restrict__ W2,
                 const float* __restrict__ b2,
                 float* __restrict__ out) {
    extern __shared__ char smem[];
    const int tid  = threadIdx.x;
    const int warp = tid >> 5;
    const int ibase = blockIdx.y * I_TILE;
    const int jblk  = blockIdx.x * (J_TILE * JITERS);

    const int i  = ibase + (tid >> 4);     // this thread's i (fixed all iters)
    const int jl = tid & 15;               // local j within tile

    const float cx = Coords[i * 3 + 0];
    const float cy = Coords[i * 3 + 1];
    const float cz = Coords[i * 3 + 2];

    const float4* Ar  = (const float4*)(g_A + i * HID);
    const float4* b1v = (const float4*)b1;

#if USE_TC
    const unsigned sb = smem_u32(smem);
    if (warp == 0) {
        asm volatile("tcgen05.alloc.cta_group::1.sync.aligned.shared::cta.b32 [%0], %1;"
                     :: "r"(sb + SM_TMEM), "r"(32u) : "memory");
        asm volatile("tcgen05.relinquish_alloc_permit.cta_group::1.sync.aligned;");
    }
    if (tid == 0) mbar_init(sb + SM_MBAR, 1);

    // W2 -> bf16 hi/lo tiles (once per block; SW128 K-major, 128B rows)
    for (int p = tid; p < OUT * 32; p += 128) {
        int o = p >> 5, h2 = p & 31;
        float w0 = W2[o * HID + 2 * h2];
        float w1 = W2[o * HID + 2 * h2 + 1];
        unsigned hi = cvt2bf16(w1, w0);
        float r0 = w0 - __uint_as_float(hi << 16);
        float r1 = w1 - __uint_as_float(hi & 0xFFFF0000u);
        unsigned lo = cvt2bf16(r1, r0);
        unsigned off = (unsigned)(o * 128 + h2 * 4);
        unsigned sw = SWZ(off);
        *(unsigned*)(smem + SM_WHI + sw) = hi;
        *(unsigned*)(smem + SM_WLO + sw) = lo;
    }
    __syncthreads();

    unsigned tmem;
    asm("ld.shared.b32 %0, [%1];" : "=r"(tmem) : "r"(sb + SM_TMEM));

    const unsigned long long ahiD = sdesc(sb + SM_AHI);
    const unsigned long long aloD = sdesc(sb + SM_ALO);
    const unsigned long long whiD = sdesc(sb + SM_WHI);
    const unsigned long long wloD = sdesc(sb + SM_WLO);

    for (int it = 0; it < JITERS; ++it) {
        const int jbase = jblk + it * J_TILE;

        // ---- stage B j-tile coalesced: 16 rows x 64 f, padded stride 68 ----
        {
            const float4* src = (const float4*)(g_B + jbase * HID);
#pragma unroll
            for (int p = tid; p < 256; p += 128) {
                int jj = p >> 4, c4 = p & 15;
                *(float4*)(smem + SM_BS + (jj * 68 + c4 * 4) * 4) = src[p];
            }
        }
        __syncthreads();   // Bs visible; also all warps past prior LDTM

        const int j = jbase + jl;
        float dx = cx - Coords[j * 3 + 0];
        float dy = cy - Coords[j * 3 + 1];
        float dz = cz - Coords[j * 3 + 2];
        float d2 = dx * dx + dy * dy + dz * dz;
        float dist = (d2 > 0.f) ? d2 * rsqrtf(d2) : 0.f;
        const float w = Edges[(size_t)i * N_NODES + j] * dist;

        const float* Brow = (const float*)(smem + SM_BS) + jl * 68;

        // ---- h1 = swish(w*(A+B)+b1), hi/lo split, STS.128 ----
#pragma unroll
        for (int c = 0; c < 8; ++c) {
            float4 a0 = __ldg(Ar + 2 * c);
            float4 a1 = __ldg(Ar + 2 * c + 1);
            float4 p0 = *(const float4*)(Brow + 8 * c);
            float4 p1 = *(const float4*)(Brow + 8 * c + 4);
            float4 q0 = __ldg(b1v + 2 * c);
            float4 q1 = __ldg(b1v + 2 * c + 1);

            float g0 = swish_fast(fmaf(w, a0.x + p0.x, q0.x));
            float g1 = swish_fast(fmaf(w, a0.y + p0.y, q0.y));
            float g2 = swish_fast(fmaf(w, a0.z + p0.z, q0.z));
            float g3 = swish_fast(fmaf(w, a0.w + p0.w, q0.w));
            float g4 = swish_fast(fmaf(w, a1.x + p1.x, q1.x));
            float g5 = swish_fast(fmaf(w, a1.y + p1.y, q1.y));
            float g6 = swish_fast(fmaf(w, a1.z + p1.z, q1.z));
            float g7 = swish_fast(fmaf(w, a1.w + p1.w, q1.w));

            unsigned h01 = cvt2bf16(g1, g0);
            unsigned h23 = cvt2bf16(g3, g2);
            unsigned h45 = cvt2bf16(g5, g4);
            unsigned h67 = cvt2bf16(g7, g6);
            float r0 = g0 - __uint_as_float(h01 << 16);
            float r1 = g1 - __uint_as_float(h01 & 0xFFFF0000u);
            float r2 = g2 - __uint_as_float(h23 << 16);
            float r3 = g3 - __uint_as_float(h23 & 0xFFFF0000u);
            float r4 = g4 - __uint_as_float(h45 << 16);
            float r5 = g5 - __uint_as_float(h45 & 0xFFFF0000u);
            float r6 = g6 - __uint_as_float(h67 << 16);
            float r7 = g7 - __uint_as_float(h67 & 0xFFFF0000u);
            unsigned l01 = cvt2bf16(r1, r0);
            unsigned l23 = cvt2bf16(r3, r2);
            unsigned l45 = cvt2bf16(r5, r4);
            unsigned l67 = cvt2bf16(r7, r6);

            unsigned off = (unsigned)(tid * 128 + c * 16);
            unsigned sw = SWZ(off);
            *(uint4*)(smem + SM_AHI + sw) = make_uint4(h01, h23, h45, h67);
            *(uint4*)(smem + SM_ALO + sw) = make_uint4(l01, l23, l45, l67);
        }

        asm volatile("fence.proxy.async.shared::cta;" ::: "memory");
        __syncthreads();

        // ---- MMA: D = Ahi*Whi + Alo*Whi + Ahi*Wlo (12 dispatches, K=64) ----
        if (warp == 0 && elect_one()) {
            unsigned en = 0;
#pragma unroll
            for (int k = 0; k < 4; ++k) { mma_f16_ss(tmem, ahiD + 2 * k, whiD + 2 * k, en); en = 1; }
#pragma unroll
            for (int k = 0; k < 4; ++k) { mma_f16_ss(tmem, aloD + 2 * k, whiD + 2 * k, 1); }
#pragma unroll
            for (int k = 0; k < 4; ++k) { mma_f16_ss(tmem, ahiD + 2 * k, wloD + 2 * k, 1); }
            asm volatile(
                "tcgen05.commit.cta_group::1.mbarrier::arrive::one.shared::cluster.b64 [%0];"
                :: "r"(sb + SM_MBAR) : "memory");
        }

        mbar_wait(sb + SM_MBAR, it & 1);
        asm volatile("tcgen05.fence::after_thread_sync;" ::: "memory");

        // ---- epilogue: LDTM, +b2, swish, store ----
        unsigned d[32];
        asm volatile(
            "tcgen05.ld.sync.aligned.32x32b.x32.b32 "
            "{%0, %1, %2, %3, %4, %5, %6, %7, "
            " %8, %9, %10, %11, %12, %13, %14, %15, "
            " %16, %17, %18, %19, %20, %21, %22, %23, "
            " %24, %25, %26, %27, %28, %29, %30, %31}, [%32];"
            : "=r"(d[0]),  "=r"(d[1]),  "=r"(d[2]),  "=r"(d[3]),
              "=r"(d[4]),  "=r"(d[5]),  "=r"(d[6]),  "=r"(d[7]),
              "=r"(d[8]),  "=r"(d[9]),  "=r"(d[10]), "=r"(d[11]),
              "=r"(d[12]), "=r"(d[13]), "=r"(d[14]), "=r"(d[15]),
              "=r"(d[16]), "=r"(d[17]), "=r"(d[18]), "=r"(d[19]),
              "=r"(d[20]), "=r"(d[21]), "=r"(d[22]), "=r"(d[23]),
              "=r"(d[24]), "=r"(d[25]), "=r"(d[26]), "=r"(d[27]),
              "=r"(d[28]), "=r"(d[29]), "=r"(d[30]), "=r"(d[31])
            : "r"(tmem));
        asm volatile("tcgen05.wait::ld.sync.aligned;" ::: "memory");
        asm volatile("tcgen05.fence::before_thread_sync;" ::: "memory");

        const size_t orow = ((size_t)i * N_NODES + j) * OUT;
        const float4* b2v = (const float4*)b2;
#pragma unroll
        for (int q = 0; q < 8; ++q) {
            float4 bq = __ldg(b2v + q);
            float4 v;
            v.x = swish_fast(__uint_as_float(d[4 * q + 0]) + bq.x);
            v.y = swish_fast(__uint_as_float(d[4 * q + 1]) + bq.y);
            v.z = swish_fast(__uint_as_float(d[4 * q + 2]) + bq.z);
            v.w = swish_fast(__uint_as_float(d[4 * q + 3]) + bq.w);
            *(float4*)(out + orow + 4 * q) = v;
        }
    }

    __syncthreads();
    if (tid == 0) mbar_inval(sb + SM_MBAR);
    __syncthreads();
    if (warp == 0) {
        asm volatile("tcgen05.dealloc.cta_group::1.sync.aligned.b32 %0, %1;"
                     :: "r"(tmem), "r"(32u));
    }
#else
    // ===================== scalar FFMA2 fallback =====================
    float2* W2p = (float2*)(smem + FB_W2P);
    float*  b1s = (float*)(smem + FB_B1);
    float*  b2s = (float*)(smem + FB_B2);
    for (int p = tid; p < HID * 16; p += 128) {
        int h = p >> 4, o2 = p & 15;
        W2p[h * 16 + o2] = make_float2(W2[(2 * o2) * HID + h],
                                       W2[(2 * o2 + 1) * HID + h]);
    }
    if (tid < HID) b1s[tid] = b1[tid];
    if (tid < OUT) b2s[tid] = b2[tid];
    __syncthreads();

    const unsigned w2sm = smem_u32(W2p);

    for (int it = 0; it < JITERS; ++it) {
        const int j = jblk + it * J_TILE + jl;
        float dx = cx - Coords[j * 3 + 0];
        float dy = cy - Coords[j * 3 + 1];
        float dz = cz - Coords[j * 3 + 2];
        float d2 = dx * dx + dy * dy + dz * dz;
        float dist = (d2 > 0.f) ? d2 * rsqrtf(d2) : 0.f;
        const float w = Edges[(size_t)i * N_NODES + j] * dist;

        const float4* Br = (const float4*)(g_B + j * HID);
        unsigned long long acc[16];
#pragma unroll
        for (int o2 = 0; o2 < 16; ++o2) acc[o2] = 0ull;

#pragma unroll 4
        for (int c = 0; c < 16; ++c) {
            float4 a  = __ldg(Ar + c);
            float4 bb = __ldg(Br + c);
            float4 bv = __ldg(((const float4*)b1) + c);
            float av[4] = {a.x, a.y, a.z, a.w};
            float pv[4] = {bb.x, bb.y, bb.z, bb.w};
            float cv[4] = {bv.x, bv.y, bv.z, bv.w};
#pragma unroll
            for (int k = 0; k < 4; ++k) {
                float g = swish_fast(fmaf(w, av[k] + pv[k], cv[k]));
                unsigned long long g2 = pack2(g, g);
                unsigned base = w2sm + (unsigned)(4 * c + k) * (16 * 8);
#pragma unroll
                for (int o2 = 0; o2 < 16; ++o2) {
                    unsigned long long wv = lds_u64(base + o2 * 8);
                    FFMA2(acc[o2], g2, wv);
                }
            }
        }

        const size_t orow = ((size_t)i * N_NODES + j) * OUT;
#pragma unroll
        for (int o4 = 0; o4 < 8; ++o4) {
            float a, b, c, d;
            unpack2(acc[2 * o4 + 0], a, b);
            unpack2(acc[2 * o4 + 1], c, d);
            float4 v;
            v.x = swish_fast(a + b2s[4 * o4 + 0]);
            v.y = swish_fast(b + b2s[4 * o4 + 1]);
            v.z = swish_fast(c + b2s[4 * o4 + 2]);
            v.w = swish_fast(d + b2s[4 * o4 + 3]);
            *(float4*)(out + orow + 4 * o4) = v;
        }
    }
#endif
}

// ---------------------------------------------------------------------------
// Harness entry. Inputs: Edges, Coordinates, Embeddings, W1, b1, W2, b2.
// Output: float32 (N, N, OUT).
// ---------------------------------------------------------------------------
extern "C" void kernel_launch(void* const* d_in, const int* in_sizes, int n_in,
                              void* d_out, int out_size) {
    const float* Edges  = (const float*)d_in[0];
    const float* Coords = (const float*)d_in[1];
    const float* Emb    = (const float*)d_in[2];
    const float* W1     = (const float*)d_in[3];
    const float* b1     = (const float*)d_in[4];
    const float* W2     = (const float*)d_in[5];
    const float* b2     = (const float*)d_in[6];
    float* out = (float*)d_out;

    precompute_AB<<<(N_NODES * HID) / 256, 256>>>(Emb, W1);

    dim3 grid(N_NODES / (J_TILE * JITERS), N_NODES / I_TILE);  // (8, 128)
    edge_mlp_tc<<<grid, 128, SM_TOTAL>>>(Edges, Coords, b1, W2, b2, out);
}

// round 6
// speedup vs baseline: 1.9415x; 1.0652x over previous
#include <cuda_runtime.h>
#include <cuda_bf16.h>
#include <cuda_fp16.h>
#include <cstdint>
#include <cstddef>

#define N_NODES 1024
#define F_IN    32
#define HID     64
#define OUT     32
#define I_TILE  8
#define J_TILE  16
#define JITERS  8     // j-tiles per block

#if defined(__CUDA_ARCH__) && (defined(__CUDA_ARCH_FEAT_SM103_ALL) || \
                               defined(__CUDA_ARCH_FEAT_SM100_ALL) || \
                               defined(__CUDA_ARCH_FAMILY_SPECIFIC__))
#define USE_TC 1
#else
#define USE_TC 0
#endif

__device__ float g_A[N_NODES * HID];   // A[i,h] = Emb[i,:] . W1[h, :F]
__device__ float g_B[N_NODES * HID];   // B[j,h] = Emb[j,:] . W1[h, F:]

// ---------------------------------------------------------------------------
// Kernel 1: A/B precompute (tiny)
// ---------------------------------------------------------------------------
__global__ void precompute_AB(const float* __restrict__ Emb,
                              const float* __restrict__ W1) {
    int idx = blockIdx.x * blockDim.x + threadIdx.x;
    int i = idx >> 6;
    int h = idx & 63;
    const float* er = Emb + i * F_IN;
    const float* wr = W1 + h * (2 * F_IN);
    float sa = 0.f, sb = 0.f;
#pragma unroll
    for (int f = 0; f < F_IN; ++f) {
        float e = er[f];
        sa = fmaf(e, wr[f], sa);
        sb = fmaf(e, wr[F_IN + f], sb);
    }
    g_A[idx] = sa;
    g_B[idx] = sb;
}

// ---------------------------------------------------------------------------
// Helpers
// ---------------------------------------------------------------------------
__device__ __forceinline__ unsigned smem_u32(const void* p) {
    unsigned a;
    asm("{ .reg .u64 t; cvta.to.shared.u64 t, %1; cvt.u32.u64 %0, t; }"
        : "=r"(a) : "l"(p));
    return a;
}

__device__ __forceinline__ unsigned long long pack2(float lo, float hi) {
    unsigned long long r;
    asm("mov.b64 %0, {%1, %2};"
        : "=l"(r) : "r"(__float_as_uint(lo)), "r"(__float_as_uint(hi)));
    return r;
}

__device__ __forceinline__ void unpack2(unsigned long long v, float& lo, float& hi) {
    unsigned a, b;
    asm("mov.b64 {%0, %1}, %2;" : "=r"(a), "=r"(b) : "l"(v));
    lo = __uint_as_float(a);
    hi = __uint_as_float(b);
}

__device__ __forceinline__ unsigned long long lds_u64(unsigned addr) {
    unsigned long long r;
    asm volatile("ld.shared.b64 %0, [%1];" : "=l"(r) : "r"(addr));
    return r;
}

#define FFMA2(acc, a, b) \
    asm("fma.rn.f32x2 %0, %1, %2, %0;" : "+l"(acc) : "l"(a), "l"(b))

__device__ __forceinline__ float swish_fast(float x) {
    float e;
    asm("ex2.approx.f32 %0, %1;" : "=f"(e) : "f"(x * (-1.442695040888963f)));
    float r;
    asm("rcp.approx.f32 %0, %1;" : "=f"(r) : "f"(1.0f + e));
    return x * r;
}

// pack two f32 -> f16x2 (first arg -> low half)
__device__ __forceinline__ unsigned cvt2f16(float lo, float hi) {
    unsigned r;
    asm("cvt.rn.f16x2.f32 %0, %1, %2;" : "=r"(r) : "f"(hi), "f"(lo));
    return r;
}

#if USE_TC
__device__ __forceinline__ bool elect_one() {
    unsigned pred;
    asm volatile("{\n\t.reg .pred p;\n\telect.sync _|p, 0xFFFFFFFF;\n\t"
                 "selp.b32 %0, 1, 0, p;\n\t}" : "=r"(pred));
    return pred != 0;
}

__device__ __forceinline__ void mbar_init(unsigned addr, unsigned cnt) {
    asm volatile("mbarrier.init.shared.b64 [%0], %1;" :: "r"(addr), "r"(cnt) : "memory");
}

__device__ __forceinline__ void mbar_inval(unsigned addr) {
    asm volatile("mbarrier.inval.shared.b64 [%0];" :: "r"(addr) : "memory");
}

__device__ __forceinline__ void mbar_wait(unsigned addr, unsigned parity) {
    asm volatile(
        "{\n\t.reg .pred P;\n\t"
        "WL_%=:\n\t"
        "mbarrier.try_wait.parity.acquire.cta.shared::cta.b64 P, [%0], %1, 0x989680;\n\t"
        "@P bra.uni WD_%=;\n\t"
        "bra.uni WL_%=;\n\t"
        "WD_%=:\n\t}"
        :: "r"(addr), "r"(parity) : "memory");
}

// SW128 K-major smem descriptor: layout=2, version=1, SBO=64, LBO=1
__device__ __forceinline__ unsigned long long sdesc(unsigned addr) {
    const unsigned long long base =
        (2ull << 61) | (1ull << 46) | (64ull << 32) | (1ull << 16);
    return base | ((unsigned long long)(addr >> 4) & 0x3FFF);
}

// idesc kind::f16: dtype=F32, atype=btype=F16(0), N=32, M=128 -> 0x8080010
#define MMA_IDESC ((1u << 4) | ((OUT / 8) << 17) | (8u << 24))

__device__ __forceinline__ void mma_f16_ss(unsigned d_tmem,
                                           unsigned long long a_desc,
                                           unsigned long long b_desc,
                                           unsigned en) {
    asm volatile(
        "{\n\t.reg .pred p;\n\t"
        "setp.ne.u32 p, %5, 0;\n\t"
        "tcgen05.mma.cta_group::1.kind::f16 [%0], %1, %2, %3, {%4, %4, %4, %4}, p;\n\t"
        "}"
        :: "r"(d_tmem), "l"(a_desc), "l"(b_desc), "r"(MMA_IDESC), "r"(0u), "r"(en)
        : "memory");
}
#endif  // USE_TC

// ---------------------------------------------------------------------------
// Dynamic SMEM layout (all MMA tiles 1024-aligned). Total 46080 B < 48K.
// ---------------------------------------------------------------------------
#define SM_TMEM  0
#define SM_MBAR0 8
#define SM_MBAR1 16
#define SM_A0    1024                     // fp16 A tile 0 (128 x 64 f16 = 16KB)
#define SM_A1    (SM_A0 + 16384)          // 17408
#define SM_WHI   (SM_A1 + 16384)          // 33792 (32 x 64 f16 = 4KB)
#define SM_WLO   (SM_WHI + 4096)          // 37888
#define SM_BS    (SM_WLO + 4096)          // 41984 (16 rows x 64 f, XOR layout)
#define SM_TOTAL (SM_BS + 4096)           // 46080

// Fallback layout (front of same buffer)
#define FB_W2P  0
#define FB_B1   (FB_W2P + HID * 16 * 8)
#define FB_B2   (FB_B1 + HID * 4)

#define SWZ(off) ((off) ^ (((off) >> 3) & 0x70))
// Bs addressing: row jl (256B), float4 slot c4 stored at (c4 ^ jl)*16
#define BS_ADDR(jl, c4) (SM_BS + ((jl) << 8) + ((unsigned)((c4) ^ (jl)) << 4))

// ---------------------------------------------------------------------------
// Kernel 2: fused edge MLP, software-pipelined over 8 j-tiles per block.
// Block = 128 thr; per iter: tile 8 i x 16 j (M=128), N=32, K=64.
// Pipeline: MMA[t] runs while epilogue[t-1] executes; h1[t+1] then overlaps
// the tail of MMA[t].
// ---------------------------------------------------------------------------
__global__ __launch_bounds__(128)
void edge_mlp_tc(const float* __restrict__ Edges,
                 const float* __restrict__ Coords,
                 const float* __restrict__ b1,
                 const float* __restrict__ W2,
                 const float* __restrict__ b2,
                 float* __restrict__ out) {
    extern __shared__ char smem[];
    const int tid  = threadIdx.x;
    const int warp = tid >> 5;
    const int ibase = blockIdx.y * I_TILE;
    const int jblk  = blockIdx.x * (J_TILE * JITERS);

    const int i  = ibase + (tid >> 4);
    const int jl = tid & 15;

    const float cx = Coords[i * 3 + 0];
    const float cy = Coords[i * 3 + 1];
    const float cz = Coords[i * 3 + 2];

    const float4* Ar  = (const float4*)(g_A + i * HID);
    const float4* b1v = (const float4*)b1;

#if USE_TC
    const unsigned sb = smem_u32(smem);
    if (warp == 0) {
        asm volatile("tcgen05.alloc.cta_group::1.sync.aligned.shared::cta.b32 [%0], %1;"
                     :: "r"(sb + SM_TMEM), "r"(64u) : "memory");
        asm volatile("tcgen05.relinquish_alloc_permit.cta_group::1.sync.aligned;");
    }
    if (tid == 0) {
        mbar_init(sb + SM_MBAR0, 1);
        mbar_init(sb + SM_MBAR1, 1);
    }

    // W2 -> fp16 hi/lo tiles (once; SW128 K-major, 128B rows)
    for (int p = tid; p < OUT * 32; p += 128) {
        int o = p >> 5, h2 = p & 31;
        float w0 = W2[o * HID + 2 * h2];
        float w1 = W2[o * HID + 2 * h2 + 1];
        unsigned hi = cvt2f16(w0, w1);
        float r0 = w0 - __half2float(__ushort_as_half((unsigned short)(hi & 0xFFFF)));
        float r1 = w1 - __half2float(__ushort_as_half((unsigned short)(hi >> 16)));
        unsigned lo = cvt2f16(r0, r1);
        unsigned sw = SWZ((unsigned)(o * 128 + h2 * 4));
        *(unsigned*)(smem + SM_WHI + sw) = hi;
        *(unsigned*)(smem + SM_WLO + sw) = lo;
    }
    __syncthreads();

    unsigned tmem;
    asm("ld.shared.b32 %0, [%1];" : "=r"(tmem) : "r"(sb + SM_TMEM));

    const unsigned long long a0D  = sdesc(sb + SM_A0);
    const unsigned long long a1D  = sdesc(sb + SM_A1);
    const unsigned long long whiD = sdesc(sb + SM_WHI);
    const unsigned long long wloD = sdesc(sb + SM_WLO);
    const float4* b2v = (const float4*)b2;

    size_t orow_prev = 0;

    for (int t = 0; t < JITERS; ++t) {
        const int jbase = jblk + t * J_TILE;

        // ---- stage B j-tile (coalesced, XOR layout) ----
        {
            const float4* src = (const float4*)(g_B + jbase * HID);
#pragma unroll
            for (int p = tid; p < 256; p += 128) {
                int jj = p >> 4, c4 = p & 15;
                *(float4*)(smem + BS_ADDR(jj, c4)) = src[p];
            }
        }
        __syncthreads();   // Bs visible to all lanes

        const int j = jbase + jl;
        float dx = cx - Coords[j * 3 + 0];
        float dy = cy - Coords[j * 3 + 1];
        float dz = cz - Coords[j * 3 + 2];
        float d2 = dx * dx + dy * dy + dz * dz;
        float dist = (d2 > 0.f) ? d2 * rsqrtf(d2) : 0.f;
        const float w = Edges[(size_t)i * N_NODES + j] * dist;

        // ---- h1 = swish(w*(A+B)+b1) -> fp16, STS.128 into Abuf[t%2] ----
        const unsigned abase = (t & 1) ? SM_A1 : SM_A0;
#pragma unroll
        for (int c = 0; c < 8; ++c) {
            float4 a0 = __ldg(Ar + 2 * c);
            float4 a1 = __ldg(Ar + 2 * c + 1);
            float4 p0 = *(const float4*)(smem + BS_ADDR(jl, 2 * c));
            float4 p1 = *(const float4*)(smem + BS_ADDR(jl, 2 * c + 1));
            float4 q0 = __ldg(b1v + 2 * c);
            float4 q1 = __ldg(b1v + 2 * c + 1);

            float g0 = swish_fast(fmaf(w, a0.x + p0.x, q0.x));
            float g1 = swish_fast(fmaf(w, a0.y + p0.y, q0.y));
            float g2 = swish_fast(fmaf(w, a0.z + p0.z, q0.z));
            float g3 = swish_fast(fmaf(w, a0.w + p0.w, q0.w));
            float g4 = swish_fast(fmaf(w, a1.x + p1.x, q1.x));
            float g5 = swish_fast(fmaf(w, a1.y + p1.y, q1.y));
            float g6 = swish_fast(fmaf(w, a1.z + p1.z, q1.z));
            float g7 = swish_fast(fmaf(w, a1.w + p1.w, q1.w));

            uint4 v = make_uint4(cvt2f16(g0, g1), cvt2f16(g2, g3),
                                 cvt2f16(g4, g5), cvt2f16(g6, g7));
            unsigned sw = SWZ((unsigned)(tid * 128 + c * 16));
            *(uint4*)(smem + abase + sw) = v;
        }

        asm volatile("fence.proxy.async.shared::cta;" ::: "memory");
        __syncthreads();

        // ---- issue MMA[t]: D[t%2] = A * (Whi + Wlo), 8 dispatches ----
        if (warp == 0 && elect_one()) {
            const unsigned long long aD = (t & 1) ? a1D : a0D;
            const unsigned dtm = tmem + (t & 1) * 32;
            unsigned en = 0;
#pragma unroll
            for (int k = 0; k < 4; ++k) { mma_f16_ss(dtm, aD + 2 * k, whiD + 2 * k, en); en = 1; }
#pragma unroll
            for (int k = 0; k < 4; ++k) { mma_f16_ss(dtm, aD + 2 * k, wloD + 2 * k, 1); }
            asm volatile(
                "tcgen05.commit.cta_group::1.mbarrier::arrive::one.shared::cluster.b64 [%0];"
                :: "r"(sb + SM_MBAR0 + (unsigned)(t & 1) * 8) : "memory");
        }

        // ---- epilogue of tile t-1 (overlaps MMA[t]) ----
        if (t > 0) {
            const int tp = t - 1;
            mbar_wait(sb + SM_MBAR0 + (unsigned)(tp & 1) * 8, (tp >> 1) & 1);
            asm volatile("tcgen05.fence::after_thread_sync;" ::: "memory");

            unsigned d[32];
            asm volatile(
                "tcgen05.ld.sync.aligned.32x32b.x32.b32 "
                "{%0, %1, %2, %3, %4, %5, %6, %7, "
                " %8, %9, %10, %11, %12, %13, %14, %15, "
                " %16, %17, %18, %19, %20, %21, %22, %23, "
                " %24, %25, %26, %27, %28, %29, %30, %31}, [%32];"
                : "=r"(d[0]),  "=r"(d[1]),  "=r"(d[2]),  "=r"(d[3]),
                  "=r"(d[4]),  "=r"(d[5]),  "=r"(d[6]),  "=r"(d[7]),
                  "=r"(d[8]),  "=r"(d[9]),  "=r"(d[10]), "=r"(d[11]),
                  "=r"(d[12]), "=r"(d[13]), "=r"(d[14]), "=r"(d[15]),
                  "=r"(d[16]), "=r"(d[17]), "=r"(d[18]), "=r"(d[19]),
                  "=r"(d[20]), "=r"(d[21]), "=r"(d[22]), "=r"(d[23]),
                  "=r"(d[24]), "=r"(d[25]), "=r"(d[26]), "=r"(d[27]),
                  "=r"(d[28]), "=r"(d[29]), "=r"(d[30]), "=r"(d[31])
                : "r"(tmem + (unsigned)(tp & 1) * 32));
            asm volatile("tcgen05.wait::ld.sync.aligned;" ::: "memory");
            asm volatile("tcgen05.fence::before_thread_sync;" ::: "memory");

#pragma unroll
            for (int q = 0; q < 8; ++q) {
                float4 bq = __ldg(b2v + q);
                float4 v;
                v.x = swish_fast(__uint_as_float(d[4 * q + 0]) + bq.x);
                v.y = swish_fast(__uint_as_float(d[4 * q + 1]) + bq.y);
                v.z = swish_fast(__uint_as_float(d[4 * q + 2]) + bq.z);
                v.w = swish_fast(__uint_as_float(d[4 * q + 3]) + bq.w);
                *(float4*)(out + orow_prev + 4 * q) = v;
            }
        }
        orow_prev = ((size_t)i * N_NODES + j) * OUT;
    }

    // ---- tail epilogue (tile JITERS-1) ----
    {
        const int tp = JITERS - 1;
        mbar_wait(sb + SM_MBAR0 + (unsigned)(tp & 1) * 8, (tp >> 1) & 1);
        asm volatile("tcgen05.fence::after_thread_sync;" ::: "memory");

        unsigned d[32];
        asm volatile(
            "tcgen05.ld.sync.aligned.32x32b.x32.b32 "
            "{%0, %1, %2, %3, %4, %5, %6, %7, "
            " %8, %9, %10, %11, %12, %13, %14, %15, "
            " %16, %17, %18, %19, %20, %21, %22, %23, "
            " %24, %25, %26, %27, %28, %29, %30, %31}, [%32];"
            : "=r"(d[0]),  "=r"(d[1]),  "=r"(d[2]),  "=r"(d[3]),
              "=r"(d[4]),  "=r"(d[5]),  "=r"(d[6]),  "=r"(d[7]),
              "=r"(d[8]),  "=r"(d[9]),  "=r"(d[10]), "=r"(d[11]),
              "=r"(d[12]), "=r"(d[13]), "=r"(d[14]), "=r"(d[15]),
              "=r"(d[16]), "=r"(d[17]), "=r"(d[18]), "=r"(d[19]),
              "=r"(d[20]), "=r"(d[21]), "=r"(d[22]), "=r"(d[23]),
              "=r"(d[24]), "=r"(d[25]), "=r"(d[26]), "=r"(d[27]),
              "=r"(d[28]), "=r"(d[29]), "=r"(d[30]), "=r"(d[31])
            : "r"(tmem + (unsigned)(tp & 1) * 32));
        asm volatile("tcgen05.wait::ld.sync.aligned;" ::: "memory");
        asm volatile("tcgen05.fence::before_thread_sync;" ::: "memory");

#pragma unroll
        for (int q = 0; q < 8; ++q) {
            float4 bq = __ldg(b2v + q);
            float4 v;
            v.x = swish_fast(__uint_as_float(d[4 * q + 0]) + bq.x);
            v.y = swish_fast(__uint_as_float(d[4 * q + 1]) + bq.y);
            v.z = swish_fast(__uint_as_float(d[4 * q + 2]) + bq.z);
            v.w = swish_fast(__uint_as_float(d[4 * q + 3]) + bq.w);
            *(float4*)(out + orow_prev + 4 * q) = v;
        }
    }

    __syncthreads();
    if (tid == 0) {
        mbar_inval(sb + SM_MBAR0);
        mbar_inval(sb + SM_MBAR1);
    }
    __syncthreads();
    if (warp == 0) {
        asm volatile("tcgen05.dealloc.cta_group::1.sync.aligned.b32 %0, %1;"
                     :: "r"(tmem), "r"(64u));
    }
#else
    // ===================== scalar FFMA2 fallback =====================
    float2* W2p = (float2*)(smem + FB_W2P);
    float*  b1s = (float*)(smem + FB_B1);
    float*  b2s = (float*)(smem + FB_B2);
    for (int p = tid; p < HID * 16; p += 128) {
        int h = p >> 4, o2 = p & 15;
        W2p[h * 16 + o2] = make_float2(W2[(2 * o2) * HID + h],
                                       W2[(2 * o2 + 1) * HID + h]);
    }
    if (tid < HID) b1s[tid] = b1[tid];
    if (tid < OUT) b2s[tid] = b2[tid];
    __syncthreads();

    const unsigned w2sm = smem_u32(W2p);

    for (int it = 0; it < JITERS; ++it) {
        const int j = jblk + it * J_TILE + jl;
        float dx = cx - Coords[j * 3 + 0];
        float dy = cy - Coords[j * 3 + 1];
        float dz = cz - Coords[j * 3 + 2];
        float d2 = dx * dx + dy * dy + dz * dz;
        float dist = (d2 > 0.f) ? d2 * rsqrtf(d2) : 0.f;
        const float w = Edges[(size_t)i * N_NODES + j] * dist;

        const float4* Br = (const float4*)(g_B + j * HID);
        unsigned long long acc[16];
#pragma unroll
        for (int o2 = 0; o2 < 16; ++o2) acc[o2] = 0ull;

#pragma unroll 4
        for (int c = 0; c < 16; ++c) {
            float4 a  = __ldg(Ar + c);
            float4 bb = __ldg(Br + c);
            float4 bv = __ldg(((const float4*)b1) + c);
            float av[4] = {a.x, a.y, a.z, a.w};
            float pv[4] = {bb.x, bb.y, bb.z, bb.w};
            float cv[4] = {bv.x, bv.y, bv.z, bv.w};
#pragma unroll
            for (int k = 0; k < 4; ++k) {
                float g = swish_fast(fmaf(w, av[k] + pv[k], cv[k]));
                unsigned long long g2 = pack2(g, g);
                unsigned base = w2sm + (unsigned)(4 * c + k) * (16 * 8);
#pragma unroll
                for (int o2 = 0; o2 < 16; ++o2) {
                    unsigned long long wv = lds_u64(base + o2 * 8);
                    FFMA2(acc[o2], g2, wv);
                }
            }
        }

        const size_t orow = ((size_t)i * N_NODES + j) * OUT;
#pragma unroll
        for (int o4 = 0; o4 < 8; ++o4) {
            float a, b, c, d;
            unpack2(acc[2 * o4 + 0], a, b);
            unpack2(acc[2 * o4 + 1], c, d);
            float4 v;
            v.x = swish_fast(a + b2s[4 * o4 + 0]);
            v.y = swish_fast(b + b2s[4 * o4 + 1]);
            v.z = swish_fast(c + b2s[4 * o4 + 2]);
            v.w = swish_fast(d + b2s[4 * o4 + 3]);
            *(float4*)(out + orow + 4 * o4) = v;
        }
    }
#endif
}

// ---------------------------------------------------------------------------
// Harness entry. Inputs: Edges, Coordinates, Embeddings, W1, b1, W2, b2.
// Output: float32 (N, N, OUT).
// ---------------------------------------------------------------------------
extern "C" void kernel_launch(void* const* d_in, const int* in_sizes, int n_in,
                              void* d_out, int out_size) {
    const float* Edges  = (const float*)d_in[0];
    const float* Coords = (const float*)d_in[1];
    const float* Emb    = (const float*)d_in[2];
    const float* W1     = (const float*)d_in[3];
    const float* b1     = (const float*)d_in[4];
    const float* W2     = (const float*)d_in[5];
    const float* b2     = (const float*)d_in[6];
    float* out = (float*)d_out;

    precompute_AB<<<(N_NODES * HID) / 256, 256>>>(Emb, W1);

    dim3 grid(N_NODES / (J_TILE * JITERS), N_NODES / I_TILE);  // (8, 128)
    edge_mlp_tc<<<grid, 128, SM_TOTAL>>>(Edges, Coords, b1, W2, b2, out);
}